// round 7
// baseline (speedup 1.0000x reference)
#include <cuda_runtime.h>
#include <cuda_fp16.h>
#include <math.h>

#define S_LEN 2048
#define E_DIM 1024
#define NH    8
#define DH    128
#define EPS_F 1e-6f

// ---------------- scratch ----------------
__device__ float g_part2[12][S_LEN][16]; // gate partials: 256e-group, s, gate(0-7 i, 8-15 f)
__device__ float g_M [NH][S_LEN];        // prefix max of a[j] = i_pre - cum
__device__ float g_n2[NH][S_LEN];        // exp(-(cum+M))
__device__ float g_E [NH][S_LEN];        // exp(a[j] - T_tile(j))
__device__ float g_T [NH][S_LEN/128];    // per-128-tile max of a
__device__ float g_Op[2][S_LEN * E_DIM]; // partial O (unnormalized), per j-half
__device__ float g_rsp[2][NH][S_LEN];    // partial rowsums, per j-half

__device__ __forceinline__ void mma16(float* d, const unsigned* a, const unsigned* b) {
    asm volatile("mma.sync.aligned.m16n8k16.row.col.f32.f16.f16.f32 "
        "{%0,%1,%2,%3}, {%4,%5,%6,%7}, {%8,%9}, {%0,%1,%2,%3};"
        : "+f"(d[0]), "+f"(d[1]), "+f"(d[2]), "+f"(d[3])
        : "r"(a[0]), "r"(a[1]), "r"(a[2]), "r"(a[3]), "r"(b[0]), "r"(b[1]));
}
__device__ __forceinline__ void ldsm4t(unsigned* r, unsigned addr) {
    asm volatile("ldmatrix.sync.aligned.m8n8.x4.trans.shared.b16 {%0,%1,%2,%3}, [%4];"
        : "=r"(r[0]), "=r"(r[1]), "=r"(r[2]), "=r"(r[3]) : "r"(addr));
}

// =================================================================
// Kernel 1: gate partials. Thread = (row, 64-e chunk): 16 private
// accumulators, zero shuffles, zero x staging. W broadcast from smem.
// grid (32, 12) = 384 CTAs, 256 thr, 3 CTA/SM -> one wave.
// =================================================================
__global__ void __launch_bounds__(256, 3)
gate_kernel(const float* __restrict__ q,
            const float* __restrict__ k,
            const float* __restrict__ v,
            const float* __restrict__ Wi,
            const float* __restrict__ Wf) {
    __shared__ float sW[256 * 16];     // [256 e][16 g]
    __shared__ float red[256 * 20];    // per-thread 16 partials, stride 20 (16B-aligned)

    int tid = threadIdx.x;
    int grp = blockIdx.y;              // 0..11: 256-e group in concat space
    int e0g = grp * 256;
    int sl  = e0g >> 10;
    int eIn = e0g & 1023;
    const float* x = (sl == 0) ? q : (sl == 1) ? k : v;

    for (int i = tid; i < 256 * 8; i += 256) {
        int e = i >> 3, g = i & 7;
        sW[e * 16 + g]     = Wi[(e0g + e) * 8 + g];
        sW[e * 16 + 8 + g] = Wf[(e0g + e) * 8 + g];
    }
    __syncthreads();

    int r = tid & 63, c = tid >> 6;    // c warp-uniform
    int row = blockIdx.x * 64 + r;
    const float* xp = x + row * E_DIM + eIn + c * 64;

    float acc[16];
    #pragma unroll
    for (int g = 0; g < 16; ++g) acc[g] = 0.f;

    #pragma unroll 4
    for (int i = 0; i < 16; ++i) {     // 16 x float4 = 64 e
        float4 x4 = *(const float4*)&xp[i * 4];
        const float* wB = &sW[(c * 64 + i * 4) * 16];
        #pragma unroll
        for (int es = 0; es < 4; ++es) {
            float xv = (es == 0) ? x4.x : (es == 1) ? x4.y : (es == 2) ? x4.z : x4.w;
            const float4 w0 = *(const float4*)&wB[es * 16 + 0];
            const float4 w1 = *(const float4*)&wB[es * 16 + 4];
            const float4 w2 = *(const float4*)&wB[es * 16 + 8];
            const float4 w3 = *(const float4*)&wB[es * 16 + 12];
            acc[0]  += xv * w0.x;  acc[1]  += xv * w0.y;
            acc[2]  += xv * w0.z;  acc[3]  += xv * w0.w;
            acc[4]  += xv * w1.x;  acc[5]  += xv * w1.y;
            acc[6]  += xv * w1.z;  acc[7]  += xv * w1.w;
            acc[8]  += xv * w2.x;  acc[9]  += xv * w2.y;
            acc[10] += xv * w2.z;  acc[11] += xv * w2.w;
            acc[12] += xv * w3.x;  acc[13] += xv * w3.y;
            acc[14] += xv * w3.z;  acc[15] += xv * w3.w;
        }
    }

    // fold the 4 c-partials inside the CTA
    float* rw = red + tid * 20;
    *(float4*)&rw[0]  = make_float4(acc[0],  acc[1],  acc[2],  acc[3]);
    *(float4*)&rw[4]  = make_float4(acc[4],  acc[5],  acc[6],  acc[7]);
    *(float4*)&rw[8]  = make_float4(acc[8],  acc[9],  acc[10], acc[11]);
    *(float4*)&rw[12] = make_float4(acc[12], acc[13], acc[14], acc[15]);
    __syncthreads();
    {
        int orow = tid >> 2, gb = (tid & 3) * 4;   // 64 rows x 4 gate-quads
        float4 sum = make_float4(0.f, 0.f, 0.f, 0.f);
        #pragma unroll
        for (int cc = 0; cc < 4; ++cc) {
            float4 t = *(const float4*)&red[(cc * 64 + orow) * 20 + gb];
            sum.x += t.x; sum.y += t.y; sum.z += t.z; sum.w += t.w;
        }
        *(float4*)&g_part2[grp][blockIdx.x * 64 + orow][gb] = sum;
    }
}

// =================================================================
// Kernel 2: reduce 12 partials + bias, shuffle scans, tile max, E.
// =================================================================
__device__ __forceinline__ float lsig(float x) {
    float m = fminf(x, 0.f);
    return m - log1pf(expf(-fabsf(x)));
}

__global__ void scan_kernel(const float* __restrict__ bi_p,
                            const float* __restrict__ bf_p) {
    int h = blockIdx.x;
    int t = threadIdx.x;
    int lane = t & 31, wid = t >> 5;
    __shared__ float wsum[32], wmax[32], tmax[32];

    float bi = bi_p[h], bf = bf_p[h];
    float i0 = bi, i1 = bi, f0 = bf, f1 = bf;
    #pragma unroll
    for (int cc = 0; cc < 12; ++cc) {
        i0 += g_part2[cc][2 * t][h];
        i1 += g_part2[cc][2 * t + 1][h];
        f0 += g_part2[cc][2 * t][h + 8];
        f1 += g_part2[cc][2 * t + 1][h + 8];
    }
    float l0 = lsig(f0), l1 = lsig(f1);

    float inc = l0 + l1;
    #pragma unroll
    for (int o = 1; o < 32; o <<= 1) {
        float n = __shfl_up_sync(0xffffffffu, inc, o);
        if (lane >= o) inc += n;
    }
    if (lane == 31) wsum[wid] = inc;
    __syncthreads();
    if (t < 32) {
        float v2 = wsum[t];
        #pragma unroll
        for (int o = 1; o < 32; o <<= 1) {
            float n = __shfl_up_sync(0xffffffffu, v2, o);
            if (t >= o) v2 += n;
        }
        wsum[t] = v2;
    }
    __syncthreads();
    float base = wid ? wsum[wid - 1] : 0.f;
    float cum1 = base + inc;
    float cum0 = cum1 - l1;

    float a0 = i0 - cum0, a1 = i1 - cum1;

    float pm = fmaxf(a0, a1);
    float incm = pm;
    #pragma unroll
    for (int o = 1; o < 32; o <<= 1) {
        float n = __shfl_up_sync(0xffffffffu, incm, o);
        if (lane >= o) incm = fmaxf(incm, n);
    }
    if (lane == 31) wmax[wid] = incm;
    __syncthreads();
    if (t < 32) {
        float v2 = wmax[t];
        #pragma unroll
        for (int o = 1; o < 32; o <<= 1) {
            float n = __shfl_up_sync(0xffffffffu, v2, o);
            if (t >= o) v2 = fmaxf(v2, n);
        }
        wmax[t] = v2;
    }
    __syncthreads();
    float basem = wid ? wmax[wid - 1] : -3.4e38f;
    float prev  = __shfl_up_sync(0xffffffffu, incm, 1);
    float exw   = lane ? prev : -3.4e38f;
    float M0 = fmaxf(fmaxf(basem, exw), a0);
    float M1 = fmaxf(M0, a1);
    g_M[h][2 * t]      = M0;
    g_M[h][2 * t + 1]  = M1;
    g_n2[h][2 * t]     = expf(-(cum0 + M0));
    g_n2[h][2 * t + 1] = expf(-(cum1 + M1));

    float mx = pm;
    #pragma unroll
    for (int off = 16; off > 0; off >>= 1)
        mx = fmaxf(mx, __shfl_xor_sync(0xffffffffu, mx, off));
    if (lane == 0) tmax[wid] = mx;
    __syncthreads();
    float T = fmaxf(tmax[wid & ~1], tmax[wid | 1]);
    if ((wid & 1) == 0 && lane == 0) g_T[h][wid >> 1] = T;
    g_E[h][2 * t]     = expf(a0 - T);
    g_E[h][2 * t + 1] = expf(a1 - T);
}

// =================================================================
// Kernel 3: fp16 TC attention, BM=128, split-j balanced (unchanged).
// =================================================================
#define STH 136

__global__ void __launch_bounds__(512, 1)
attn_kernel(const float* __restrict__ q,
            const float* __restrict__ k,
            const float* __restrict__ v) {
    extern __shared__ __half smem_h[];
    __half* Qs = smem_h;                   // [128][STH]
    __half* Ks = Qs + 128 * STH;
    __half* Vs = Ks + 128 * STH;
    __half* Ps = Vs + 128 * STH;
    float* sMq = (float*)(Ps + 128 * STH); // [128]
    float* sR  = sMq + 128;                // [128]
    float* rrs = sR + 128;                 // [4][128]

    int h    = blockIdx.y;
    int ib   = blockIdx.x;                 // 0..15
    int tid  = threadIdx.x;
    int wid  = tid >> 5, lane = tid & 31;
    int wy   = wid >> 2, wx = wid & 3;
    int g    = lane >> 2, tig = lane & 3;

    unsigned vsm = (unsigned)__cvta_generic_to_shared(Vs);
    {
        int sel = lane >> 3, l8 = lane & 7;
        vsm += (((sel & 1) * 8 + l8) * STH + wx * 32 + (sel >> 1) * 8) * 2;
    }

    const float qscale = 0.08838834764831845f;   // 1/sqrt(128)

    #pragma unroll 1
    for (int it = 0; it < 2; ++it) {
        int qt   = it ? ib : (15 - ib);
        int half = it ? 0 : 1;
        int nj   = qt + 1;
        int jlo  = half ? (nj >> 1) : 0;
        int jhi  = half ? nj : (nj >> 1);
        int i0   = qt * 128;

        __syncthreads();
        for (int idx = tid; idx < 128 * 32; idx += 512) {
            int i = idx >> 5, c4 = (idx & 31) * 4;
            float4 t4 = *(const float4*)&q[(i0 + i) * E_DIM + h * DH + c4];
            __half2 h01 = __floats2half2_rn(t4.x * qscale, t4.y * qscale);
            __half2 h23 = __floats2half2_rn(t4.z * qscale, t4.w * qscale);
            *(uint2*)&Qs[i * STH + c4] = make_uint2(*(unsigned*)&h01, *(unsigned*)&h23);
        }
        if (tid < 128) sMq[tid] = g_M[h][i0 + tid];

        float Oa[2][4][4];
        #pragma unroll
        for (int mi = 0; mi < 2; ++mi)
            #pragma unroll
            for (int nt = 0; nt < 4; ++nt)
                #pragma unroll
                for (int c = 0; c < 4; ++c) Oa[mi][nt][c] = 0.f;
        float rs[2][2] = {{0.f, 0.f}, {0.f, 0.f}};
        __syncthreads();

        for (int jt = jlo; jt < jhi; ++jt) {
            int j0 = jt * 128;
            float T = g_T[h][jt];
            for (int idx = tid; idx < 128 * 32; idx += 512) {
                int j = idx >> 5, c4 = (idx & 31) * 4;
                float e = g_E[h][j0 + j];
                float4 kt = *(const float4*)&k[(j0 + j) * E_DIM + h * DH + c4];
                __half2 k01 = __floats2half2_rn(kt.x * e, kt.y * e);
                __half2 k23 = __floats2half2_rn(kt.z * e, kt.w * e);
                *(uint2*)&Ks[j * STH + c4] = make_uint2(*(unsigned*)&k01, *(unsigned*)&k23);
                float4 vt = *(const float4*)&v[(j0 + j) * E_DIM + h * DH + c4];
                __half2 v01 = __floats2half2_rn(vt.x, vt.y);
                __half2 v23 = __floats2half2_rn(vt.z, vt.w);
                *(uint2*)&Vs[j * STH + c4] = make_uint2(*(unsigned*)&v01, *(unsigned*)&v23);
            }
            if (tid < 128) sR[tid] = __expf(T - sMq[tid]);
            __syncthreads();

            // ---- QK^T ----
            float acc[2][4][4];
            #pragma unroll
            for (int mi = 0; mi < 2; ++mi)
                #pragma unroll
                for (int nt = 0; nt < 4; ++nt)
                    #pragma unroll
                    for (int c = 0; c < 4; ++c) acc[mi][nt][c] = 0.f;

            #pragma unroll
            for (int ks = 0; ks < 8; ++ks) {
                int d0 = ks * 16;
                unsigned a[2][4], b[4][2];
                #pragma unroll
                for (int mi = 0; mi < 2; ++mi) {
                    int r0 = wy * 32 + mi * 16 + g;
                    a[mi][0] = *(const unsigned*)&Qs[r0 * STH + d0 + 2 * tig];
                    a[mi][1] = *(const unsigned*)&Qs[(r0 + 8) * STH + d0 + 2 * tig];
                    a[mi][2] = *(const unsigned*)&Qs[r0 * STH + d0 + 8 + 2 * tig];
                    a[mi][3] = *(const unsigned*)&Qs[(r0 + 8) * STH + d0 + 8 + 2 * tig];
                }
                #pragma unroll
                for (int nt = 0; nt < 4; ++nt) {
                    int jb = wx * 32 + nt * 8 + g;
                    b[nt][0] = *(const unsigned*)&Ks[jb * STH + d0 + 2 * tig];
                    b[nt][1] = *(const unsigned*)&Ks[jb * STH + d0 + 8 + 2 * tig];
                }
                #pragma unroll
                for (int mi = 0; mi < 2; ++mi)
                    #pragma unroll
                    for (int nt = 0; nt < 4; ++nt)
                        mma16(acc[mi][nt], a[mi], b[nt]);
            }

            // ---- apply R, mask, rowsum, stage P ----
            bool diag = (jt == qt);
            #pragma unroll
            for (int mi = 0; mi < 2; ++mi) {
                int rl = wy * 32 + mi * 16 + g;
                float Rl = sR[rl], Rh = sR[rl + 8];
                int iglo = i0 + rl, ighi = iglo + 8;
                #pragma unroll
                for (int nt = 0; nt < 4; ++nt) {
                    int jc = wx * 32 + nt * 8 + 2 * tig;
                    int jg = j0 + jc;
                    float p0 = acc[mi][nt][0] * Rl;
                    float p1 = acc[mi][nt][1] * Rl;
                    float p2 = acc[mi][nt][2] * Rh;
                    float p3 = acc[mi][nt][3] * Rh;
                    if (diag) {
                        if (jg     > iglo) p0 = 0.f;
                        if (jg + 1 > iglo) p1 = 0.f;
                        if (jg     > ighi) p2 = 0.f;
                        if (jg + 1 > ighi) p3 = 0.f;
                    }
                    rs[mi][0] += p0 + p1;
                    rs[mi][1] += p2 + p3;
                    *(__half2*)&Ps[rl * STH + jc]       = __floats2half2_rn(p0, p1);
                    *(__half2*)&Ps[(rl + 8) * STH + jc] = __floats2half2_rn(p2, p3);
                }
            }
            __syncthreads();

            // ---- P @ V ----
            #pragma unroll
            for (int ks = 0; ks < 8; ++ks) {
                int j8 = ks * 16;
                unsigned a[2][4], b[4][2];
                #pragma unroll
                for (int mi = 0; mi < 2; ++mi) {
                    int r0 = wy * 32 + mi * 16 + g;
                    a[mi][0] = *(const unsigned*)&Ps[r0 * STH + j8 + 2 * tig];
                    a[mi][1] = *(const unsigned*)&Ps[(r0 + 8) * STH + j8 + 2 * tig];
                    a[mi][2] = *(const unsigned*)&Ps[r0 * STH + j8 + 8 + 2 * tig];
                    a[mi][3] = *(const unsigned*)&Ps[(r0 + 8) * STH + j8 + 8 + 2 * tig];
                }
                #pragma unroll
                for (int p = 0; p < 2; ++p) {
                    unsigned r4[4];
                    ldsm4t(r4, vsm + (unsigned)((j8 * STH + p * 16) * 2));
                    b[2 * p][0]     = r4[0];
                    b[2 * p][1]     = r4[1];
                    b[2 * p + 1][0] = r4[2];
                    b[2 * p + 1][1] = r4[3];
                }
                #pragma unroll
                for (int mi = 0; mi < 2; ++mi)
                    #pragma unroll
                    for (int nt = 0; nt < 4; ++nt)
                        mma16(Oa[mi][nt], a[mi], b[nt]);
            }
            __syncthreads();
        }

        // ---- epilogue: partial rowsums + partial O to global ----
        #pragma unroll
        for (int mi = 0; mi < 2; ++mi)
            #pragma unroll
            for (int c = 0; c < 2; ++c) {
                rs[mi][c] += __shfl_xor_sync(0xffffffffu, rs[mi][c], 1);
                rs[mi][c] += __shfl_xor_sync(0xffffffffu, rs[mi][c], 2);
            }
        if (tig == 0) {
            #pragma unroll
            for (int mi = 0; mi < 2; ++mi)
                #pragma unroll
                for (int c = 0; c < 2; ++c) {
                    int row = wy * 32 + mi * 16 + g + 8 * c;
                    rrs[wx * 128 + row] = rs[mi][c];
                }
        }
        __syncthreads();
        if (tid < 128) {
            float tot = rrs[tid] + rrs[128 + tid] + rrs[256 + tid] + rrs[384 + tid];
            g_rsp[half][h][i0 + tid] = tot;
        }
        float* Op = g_Op[half];
        #pragma unroll
        for (int mi = 0; mi < 2; ++mi)
            #pragma unroll
            for (int c = 0; c < 2; ++c) {
                int row = wy * 32 + mi * 16 + g + 8 * c;
                int grow = i0 + row;
                #pragma unroll
                for (int nt = 0; nt < 4; ++nt) {
                    *(float2*)&Op[grow * E_DIM + h * DH + wx * 32 + nt * 8 + 2 * tig]
                        = make_float2(Oa[mi][nt][2 * c], Oa[mi][nt][2 * c + 1]);
                }
            }
    }
}

// =================================================================
// Kernel 4: fixup — 4 rows per block for MLP + interleaved shuffles.
// grid 512 x 256 thr; warp = head, lane = 4 cols, 4 rows each.
// =================================================================
__global__ void fixup_kernel(const float* __restrict__ lnsc,
                             float* __restrict__ out) {
    int ib = blockIdx.x;
    int h = threadIdx.x >> 5, lane = threadIdx.x & 31;
    int c4 = lane * 4;

    float4 p0[4], p1[4];
    float rsum[4], n2v[4];
    #pragma unroll
    for (int rr = 0; rr < 4; ++rr) {
        int i = ib * 4 + rr;
        int base = i * E_DIM + h * DH + c4;
        p0[rr] = *(const float4*)&g_Op[0][base];
        p1[rr] = *(const float4*)&g_Op[1][base];
        rsum[rr] = g_rsp[0][h][i] + g_rsp[1][h][i];
        n2v[rr]  = g_n2[h][i];
    }
    float4 gl = *(const float4*)&lnsc[h * DH + c4];

    float x[4][4], s[4], s2[4];
    #pragma unroll
    for (int rr = 0; rr < 4; ++rr) {
        float denom = fmaxf(fabsf(rsum[rr]), n2v[rr]) + EPS_F;
        float invd = 1.f / denom;
        x[rr][0] = (p0[rr].x + p1[rr].x) * invd;
        x[rr][1] = (p0[rr].y + p1[rr].y) * invd;
        x[rr][2] = (p0[rr].z + p1[rr].z) * invd;
        x[rr][3] = (p0[rr].w + p1[rr].w) * invd;
        s[rr]  = x[rr][0] + x[rr][1] + x[rr][2] + x[rr][3];
        s2[rr] = x[rr][0] * x[rr][0] + x[rr][1] * x[rr][1]
               + x[rr][2] * x[rr][2] + x[rr][3] * x[rr][3];
    }
    #pragma unroll
    for (int o = 16; o > 0; o >>= 1) {
        #pragma unroll
        for (int rr = 0; rr < 4; ++rr) {
            s[rr]  += __shfl_xor_sync(0xffffffffu, s[rr],  o);
            s2[rr] += __shfl_xor_sync(0xffffffffu, s2[rr], o);
        }
    }
    #pragma unroll
    for (int rr = 0; rr < 4; ++rr) {
        float mean = s[rr] * (1.f / 128.f);
        float rstd = rsqrtf(s2[rr] * (1.f / 128.f) - mean * mean + EPS_F);
        int base = (ib * 4 + rr) * E_DIM + h * DH + c4;
        float4 o4;
        o4.x = (x[rr][0] - mean) * rstd * gl.x;
        o4.y = (x[rr][1] - mean) * rstd * gl.y;
        o4.z = (x[rr][2] - mean) * rstd * gl.z;
        o4.w = (x[rr][3] - mean) * rstd * gl.w;
        *(float4*)&out[base] = o4;
    }
}

// =================================================================
extern "C" void kernel_launch(void* const* d_in, const int* in_sizes, int n_in,
                              void* d_out, int out_size) {
    const float* q    = (const float*)d_in[0];
    const float* k    = (const float*)d_in[1];
    const float* v    = (const float*)d_in[2];
    const float* Wi   = (const float*)d_in[3];
    const float* bi   = (const float*)d_in[4];
    const float* Wf   = (const float*)d_in[5];
    const float* bf   = (const float*)d_in[6];
    const float* lnsc = (const float*)d_in[7];
    float* out = (float*)d_out;

    const int attn_smem = 4 * 128 * STH * 2 + 768 * 4;   // 142336 B

    cudaFuncSetAttribute(attn_kernel, cudaFuncAttributeMaxDynamicSharedMemorySize, attn_smem);

    gate_kernel<<<dim3(32, 12), 256>>>(q, k, v, Wi, Wf);
    scan_kernel<<<8, 1024>>>(bi, bf);
    attn_kernel<<<dim3(16, NH), 512, attn_smem>>>(q, k, v);
    fixup_kernel<<<S_LEN / 4, 256>>>(lnsc, out);
}

// round 8
// speedup vs baseline: 1.2888x; 1.2888x over previous
#include <cuda_runtime.h>
#include <cuda_fp16.h>
#include <math.h>

#define S_LEN 2048
#define E_DIM 1024
#define NH    8
#define DH    128
#define EPS_F 1e-6f

// ---------------- scratch ----------------
__device__ float g_part[6][16][S_LEN];  // gate partials: 512e-slice, gate(0-7 i, 8-15 f), s
__device__ float g_M [NH][S_LEN];       // prefix max of a[j] = i_pre - cum
__device__ float g_n2[NH][S_LEN];       // exp(-(cum+M))
__device__ float g_E [NH][S_LEN];       // exp(a[j] - T_tile(j))
__device__ float g_T [NH][S_LEN/128];   // per-128-tile max of a
__device__ float g_Op[2][S_LEN * E_DIM];// partial O (unnormalized), per j-half
__device__ float g_rsp[2][NH][S_LEN];   // partial rowsums, per j-half

__device__ __forceinline__ void mma16(float* d, const unsigned* a, const unsigned* b) {
    asm volatile("mma.sync.aligned.m16n8k16.row.col.f32.f16.f16.f32 "
        "{%0,%1,%2,%3}, {%4,%5,%6,%7}, {%8,%9}, {%0,%1,%2,%3};"
        : "+f"(d[0]), "+f"(d[1]), "+f"(d[2]), "+f"(d[3])
        : "r"(a[0]), "r"(a[1]), "r"(a[2]), "r"(a[3]), "r"(b[0]), "r"(b[1]));
}
__device__ __forceinline__ void ldsm4t(unsigned* r, unsigned addr) {
    asm volatile("ldmatrix.sync.aligned.m8n8.x4.trans.shared.b16 {%0,%1,%2,%3}, [%4];"
        : "=r"(r[0]), "=r"(r[1]), "=r"(r[2]), "=r"(r[3]) : "r"(addr));
}

// =================================================================
// Kernel 1: gate partials, pipelined staging (R6 structure), 512-e
// slices. grid (128, 6) x 256 thr, 3 CTA/SM. CTA = 16 rows x 512 e.
// Warp owns 64 e in 2 chunks of 32; prefetch chunk c+1 while computing.
// =================================================================
__global__ void __launch_bounds__(256, 3)
gate_kernel(const float* __restrict__ q,
            const float* __restrict__ k,
            const float* __restrict__ v,
            const float* __restrict__ Wi,
            const float* __restrict__ Wf) {
    extern __shared__ float gs[];
    float* sW  = gs;                  // [512][16]
    float* sX  = sW + 512 * 16;       // per warp [16][33]
    float* red = sX + 8 * 16 * 33;    // [8*32][20]

    int tid = threadIdx.x, w = tid >> 5, lane = tid & 31;
    int hs = blockIdx.y;              // 0..5: 512-e slice of concat space
    int sl = hs >> 1;
    int eIn = (hs & 1) * 512;
    const float* x = (sl == 0) ? q : (sl == 1) ? k : v;

    for (int i = tid; i < 512 * 8; i += 256) {
        int e = i >> 3, g = i & 7;
        sW[e * 16 + g]     = Wi[(sl * 1024 + eIn + e) * 8 + g];
        sW[e * 16 + 8 + g] = Wf[(sl * 1024 + eIn + e) * 8 + g];
    }
    __syncthreads();

    int r0 = blockIdx.x * 16;
    int e_off = w * 64;
    int rr = lane & 15, hh = lane >> 4;
    const float* xb = x + r0 * E_DIM + eIn + e_off;
    float* sXw = sX + w * 16 * 33;

    float acc[16];
    #pragma unroll
    for (int g = 0; g < 16; ++g) acc[g] = 0.f;

    float buf[16];
    #pragma unroll
    for (int r = 0; r < 16; ++r) buf[r] = xb[r * E_DIM + lane];

    #pragma unroll
    for (int c = 0; c < 2; ++c) {
        __syncwarp();
        #pragma unroll
        for (int r = 0; r < 16; ++r) sXw[r * 33 + lane] = buf[r];
        __syncwarp();
        if (c < 1) {
            #pragma unroll
            for (int r = 0; r < 16; ++r)
                buf[r] = xb[r * E_DIM + 32 + lane];
        }
        int eb = e_off + c * 32 + hh * 16;
        #pragma unroll
        for (int e2 = 0; e2 < 16; ++e2) {
            float xv = sXw[rr * 33 + hh * 16 + e2];
            const float4 w0 = *(const float4*)&sW[(eb + e2) * 16 + 0];
            const float4 w1 = *(const float4*)&sW[(eb + e2) * 16 + 4];
            const float4 w2 = *(const float4*)&sW[(eb + e2) * 16 + 8];
            const float4 w3 = *(const float4*)&sW[(eb + e2) * 16 + 12];
            acc[0]  += xv * w0.x;  acc[1]  += xv * w0.y;
            acc[2]  += xv * w0.z;  acc[3]  += xv * w0.w;
            acc[4]  += xv * w1.x;  acc[5]  += xv * w1.y;
            acc[6]  += xv * w1.z;  acc[7]  += xv * w1.w;
            acc[8]  += xv * w2.x;  acc[9]  += xv * w2.y;
            acc[10] += xv * w2.z;  acc[11] += xv * w2.w;
            acc[12] += xv * w3.x;  acc[13] += xv * w3.y;
            acc[14] += xv * w3.z;  acc[15] += xv * w3.w;
        }
    }

    __syncthreads();
    float* rw = red + (w * 32 + lane) * 20;
    *(float4*)&rw[0]  = make_float4(acc[0],  acc[1],  acc[2],  acc[3]);
    *(float4*)&rw[4]  = make_float4(acc[4],  acc[5],  acc[6],  acc[7]);
    *(float4*)&rw[8]  = make_float4(acc[8],  acc[9],  acc[10], acc[11]);
    *(float4*)&rw[12] = make_float4(acc[12], acc[13], acc[14], acc[15]);
    __syncthreads();
    {
        int row = tid >> 4, g = tid & 15;       // 256 = 16 rows x 16 gates
        float s = 0.f;
        #pragma unroll
        for (int w8 = 0; w8 < 8; ++w8)
            s += red[(w8 * 32 + row) * 20 + g] + red[(w8 * 32 + 16 + row) * 20 + g];
        g_part[hs][g][r0 + row] = s;
    }
}

// =================================================================
// Kernel 2: reduce 6 partials + bias, shuffle scans, tile max, E.
// =================================================================
__device__ __forceinline__ float lsig(float x) {
    float m = fminf(x, 0.f);
    return m - log1pf(expf(-fabsf(x)));
}

__global__ void scan_kernel(const float* __restrict__ bi_p,
                            const float* __restrict__ bf_p) {
    int h = blockIdx.x;
    int t = threadIdx.x;
    int lane = t & 31, wid = t >> 5;
    __shared__ float wsum[32], wmax[32], tmax[32];

    float bi = bi_p[h], bf = bf_p[h];
    float i0 = bi, i1 = bi, f0 = bf, f1 = bf;
    #pragma unroll
    for (int sl = 0; sl < 6; ++sl) {
        float2 vi = *(const float2*)&g_part[sl][h][2 * t];
        float2 vf = *(const float2*)&g_part[sl][h + 8][2 * t];
        i0 += vi.x; i1 += vi.y; f0 += vf.x; f1 += vf.y;
    }
    float l0 = lsig(f0), l1 = lsig(f1);

    float inc = l0 + l1;
    #pragma unroll
    for (int o = 1; o < 32; o <<= 1) {
        float n = __shfl_up_sync(0xffffffffu, inc, o);
        if (lane >= o) inc += n;
    }
    if (lane == 31) wsum[wid] = inc;
    __syncthreads();
    if (t < 32) {
        float v2 = wsum[t];
        #pragma unroll
        for (int o = 1; o < 32; o <<= 1) {
            float n = __shfl_up_sync(0xffffffffu, v2, o);
            if (t >= o) v2 += n;
        }
        wsum[t] = v2;
    }
    __syncthreads();
    float base = wid ? wsum[wid - 1] : 0.f;
    float cum1 = base + inc;
    float cum0 = cum1 - l1;

    float a0 = i0 - cum0, a1 = i1 - cum1;

    float pm = fmaxf(a0, a1);
    float incm = pm;
    #pragma unroll
    for (int o = 1; o < 32; o <<= 1) {
        float n = __shfl_up_sync(0xffffffffu, incm, o);
        if (lane >= o) incm = fmaxf(incm, n);
    }
    if (lane == 31) wmax[wid] = incm;
    __syncthreads();
    if (t < 32) {
        float v2 = wmax[t];
        #pragma unroll
        for (int o = 1; o < 32; o <<= 1) {
            float n = __shfl_up_sync(0xffffffffu, v2, o);
            if (t >= o) v2 = fmaxf(v2, n);
        }
        wmax[t] = v2;
    }
    __syncthreads();
    float basem = wid ? wmax[wid - 1] : -3.4e38f;
    float prev  = __shfl_up_sync(0xffffffffu, incm, 1);
    float exw   = lane ? prev : -3.4e38f;
    float M0 = fmaxf(fmaxf(basem, exw), a0);
    float M1 = fmaxf(M0, a1);
    g_M[h][2 * t]      = M0;
    g_M[h][2 * t + 1]  = M1;
    g_n2[h][2 * t]     = expf(-(cum0 + M0));
    g_n2[h][2 * t + 1] = expf(-(cum1 + M1));

    float mx = pm;
    #pragma unroll
    for (int off = 16; off > 0; off >>= 1)
        mx = fmaxf(mx, __shfl_xor_sync(0xffffffffu, mx, off));
    if (lane == 0) tmax[wid] = mx;
    __syncthreads();
    float T = fmaxf(tmax[wid & ~1], tmax[wid | 1]);
    if ((wid & 1) == 0 && lane == 0) g_T[h][wid >> 1] = T;
    g_E[h][2 * t]     = expf(a0 - T);
    g_E[h][2 * t + 1] = expf(a1 - T);
}

// =================================================================
// Kernel 3: fp16 TC attention, BM=128, split-j balanced (R6, unchanged).
// =================================================================
#define STH 136

__global__ void __launch_bounds__(512, 1)
attn_kernel(const float* __restrict__ q,
            const float* __restrict__ k,
            const float* __restrict__ v) {
    extern __shared__ __half smem_h[];
    __half* Qs = smem_h;                   // [128][STH]
    __half* Ks = Qs + 128 * STH;
    __half* Vs = Ks + 128 * STH;
    __half* Ps = Vs + 128 * STH;
    float* sMq = (float*)(Ps + 128 * STH); // [128]
    float* sR  = sMq + 128;                // [128]
    float* rrs = sR + 128;                 // [4][128]

    int h    = blockIdx.y;
    int ib   = blockIdx.x;                 // 0..15
    int tid  = threadIdx.x;
    int wid  = tid >> 5, lane = tid & 31;
    int wy   = wid >> 2, wx = wid & 3;
    int g    = lane >> 2, tig = lane & 3;

    unsigned vsm = (unsigned)__cvta_generic_to_shared(Vs);
    {
        int sel = lane >> 3, l8 = lane & 7;
        vsm += (((sel & 1) * 8 + l8) * STH + wx * 32 + (sel >> 1) * 8) * 2;
    }

    const float qscale = 0.08838834764831845f;   // 1/sqrt(128)

    #pragma unroll 1
    for (int it = 0; it < 2; ++it) {
        int qt   = it ? ib : (15 - ib);
        int half = it ? 0 : 1;
        int nj   = qt + 1;
        int jlo  = half ? (nj >> 1) : 0;
        int jhi  = half ? nj : (nj >> 1);
        int i0   = qt * 128;

        __syncthreads();
        for (int idx = tid; idx < 128 * 32; idx += 512) {
            int i = idx >> 5, c4 = (idx & 31) * 4;
            float4 t4 = *(const float4*)&q[(i0 + i) * E_DIM + h * DH + c4];
            __half2 h01 = __floats2half2_rn(t4.x * qscale, t4.y * qscale);
            __half2 h23 = __floats2half2_rn(t4.z * qscale, t4.w * qscale);
            *(uint2*)&Qs[i * STH + c4] = make_uint2(*(unsigned*)&h01, *(unsigned*)&h23);
        }
        if (tid < 128) sMq[tid] = g_M[h][i0 + tid];

        float Oa[2][4][4];
        #pragma unroll
        for (int mi = 0; mi < 2; ++mi)
            #pragma unroll
            for (int nt = 0; nt < 4; ++nt)
                #pragma unroll
                for (int c = 0; c < 4; ++c) Oa[mi][nt][c] = 0.f;
        float rs[2][2] = {{0.f, 0.f}, {0.f, 0.f}};
        __syncthreads();

        for (int jt = jlo; jt < jhi; ++jt) {
            int j0 = jt * 128;
            float T = g_T[h][jt];
            for (int idx = tid; idx < 128 * 32; idx += 512) {
                int j = idx >> 5, c4 = (idx & 31) * 4;
                float e = g_E[h][j0 + j];
                float4 kt = *(const float4*)&k[(j0 + j) * E_DIM + h * DH + c4];
                __half2 k01 = __floats2half2_rn(kt.x * e, kt.y * e);
                __half2 k23 = __floats2half2_rn(kt.z * e, kt.w * e);
                *(uint2*)&Ks[j * STH + c4] = make_uint2(*(unsigned*)&k01, *(unsigned*)&k23);
                float4 vt = *(const float4*)&v[(j0 + j) * E_DIM + h * DH + c4];
                __half2 v01 = __floats2half2_rn(vt.x, vt.y);
                __half2 v23 = __floats2half2_rn(vt.z, vt.w);
                *(uint2*)&Vs[j * STH + c4] = make_uint2(*(unsigned*)&v01, *(unsigned*)&v23);
            }
            if (tid < 128) sR[tid] = __expf(T - sMq[tid]);
            __syncthreads();

            // ---- QK^T ----
            float acc[2][4][4];
            #pragma unroll
            for (int mi = 0; mi < 2; ++mi)
                #pragma unroll
                for (int nt = 0; nt < 4; ++nt)
                    #pragma unroll
                    for (int c = 0; c < 4; ++c) acc[mi][nt][c] = 0.f;

            #pragma unroll
            for (int ks = 0; ks < 8; ++ks) {
                int d0 = ks * 16;
                unsigned a[2][4], b[4][2];
                #pragma unroll
                for (int mi = 0; mi < 2; ++mi) {
                    int r0 = wy * 32 + mi * 16 + g;
                    a[mi][0] = *(const unsigned*)&Qs[r0 * STH + d0 + 2 * tig];
                    a[mi][1] = *(const unsigned*)&Qs[(r0 + 8) * STH + d0 + 2 * tig];
                    a[mi][2] = *(const unsigned*)&Qs[r0 * STH + d0 + 8 + 2 * tig];
                    a[mi][3] = *(const unsigned*)&Qs[(r0 + 8) * STH + d0 + 8 + 2 * tig];
                }
                #pragma unroll
                for (int nt = 0; nt < 4; ++nt) {
                    int jb = wx * 32 + nt * 8 + g;
                    b[nt][0] = *(const unsigned*)&Ks[jb * STH + d0 + 2 * tig];
                    b[nt][1] = *(const unsigned*)&Ks[jb * STH + d0 + 8 + 2 * tig];
                }
                #pragma unroll
                for (int mi = 0; mi < 2; ++mi)
                    #pragma unroll
                    for (int nt = 0; nt < 4; ++nt)
                        mma16(acc[mi][nt], a[mi], b[nt]);
            }

            // ---- apply R, mask, rowsum, stage P ----
            bool diag = (jt == qt);
            #pragma unroll
            for (int mi = 0; mi < 2; ++mi) {
                int rl = wy * 32 + mi * 16 + g;
                float Rl = sR[rl], Rh = sR[rl + 8];
                int iglo = i0 + rl, ighi = iglo + 8;
                #pragma unroll
                for (int nt = 0; nt < 4; ++nt) {
                    int jc = wx * 32 + nt * 8 + 2 * tig;
                    int jg = j0 + jc;
                    float p0 = acc[mi][nt][0] * Rl;
                    float p1 = acc[mi][nt][1] * Rl;
                    float p2 = acc[mi][nt][2] * Rh;
                    float p3 = acc[mi][nt][3] * Rh;
                    if (diag) {
                        if (jg     > iglo) p0 = 0.f;
                        if (jg + 1 > iglo) p1 = 0.f;
                        if (jg     > ighi) p2 = 0.f;
                        if (jg + 1 > ighi) p3 = 0.f;
                    }
                    rs[mi][0] += p0 + p1;
                    rs[mi][1] += p2 + p3;
                    *(__half2*)&Ps[rl * STH + jc]       = __floats2half2_rn(p0, p1);
                    *(__half2*)&Ps[(rl + 8) * STH + jc] = __floats2half2_rn(p2, p3);
                }
            }
            __syncthreads();

            // ---- P @ V ----
            #pragma unroll
            for (int ks = 0; ks < 8; ++ks) {
                int j8 = ks * 16;
                unsigned a[2][4], b[4][2];
                #pragma unroll
                for (int mi = 0; mi < 2; ++mi) {
                    int r0 = wy * 32 + mi * 16 + g;
                    a[mi][0] = *(const unsigned*)&Ps[r0 * STH + j8 + 2 * tig];
                    a[mi][1] = *(const unsigned*)&Ps[(r0 + 8) * STH + j8 + 2 * tig];
                    a[mi][2] = *(const unsigned*)&Ps[r0 * STH + j8 + 8 + 2 * tig];
                    a[mi][3] = *(const unsigned*)&Ps[(r0 + 8) * STH + j8 + 8 + 2 * tig];
                }
                #pragma unroll
                for (int p = 0; p < 2; ++p) {
                    unsigned r4[4];
                    ldsm4t(r4, vsm + (unsigned)((j8 * STH + p * 16) * 2));
                    b[2 * p][0]     = r4[0];
                    b[2 * p][1]     = r4[1];
                    b[2 * p + 1][0] = r4[2];
                    b[2 * p + 1][1] = r4[3];
                }
                #pragma unroll
                for (int mi = 0; mi < 2; ++mi)
                    #pragma unroll
                    for (int nt = 0; nt < 4; ++nt)
                        mma16(Oa[mi][nt], a[mi], b[nt]);
            }
            __syncthreads();
        }

        // ---- epilogue: partial rowsums + partial O to global ----
        #pragma unroll
        for (int mi = 0; mi < 2; ++mi)
            #pragma unroll
            for (int c = 0; c < 2; ++c) {
                rs[mi][c] += __shfl_xor_sync(0xffffffffu, rs[mi][c], 1);
                rs[mi][c] += __shfl_xor_sync(0xffffffffu, rs[mi][c], 2);
            }
        if (tig == 0) {
            #pragma unroll
            for (int mi = 0; mi < 2; ++mi)
                #pragma unroll
                for (int c = 0; c < 2; ++c) {
                    int row = wy * 32 + mi * 16 + g + 8 * c;
                    rrs[wx * 128 + row] = rs[mi][c];
                }
        }
        __syncthreads();
        if (tid < 128) {
            float tot = rrs[tid] + rrs[128 + tid] + rrs[256 + tid] + rrs[384 + tid];
            g_rsp[half][h][i0 + tid] = tot;
        }
        float* Op = g_Op[half];
        #pragma unroll
        for (int mi = 0; mi < 2; ++mi)
            #pragma unroll
            for (int c = 0; c < 2; ++c) {
                int row = wy * 32 + mi * 16 + g + 8 * c;
                int grow = i0 + row;
                #pragma unroll
                for (int nt = 0; nt < 4; ++nt) {
                    *(float2*)&Op[grow * E_DIM + h * DH + wx * 32 + nt * 8 + 2 * tig]
                        = make_float2(Oa[mi][nt][2 * c], Oa[mi][nt][2 * c + 1]);
                }
            }
    }
}

// =================================================================
// Kernel 4: fixup — 2 rows per block. grid 1024 x 256 thr.
// =================================================================
__global__ void fixup_kernel(const float* __restrict__ lnsc,
                             float* __restrict__ out) {
    int ib = blockIdx.x;
    int h = threadIdx.x >> 5, lane = threadIdx.x & 31;
    int c4 = lane * 4;

    float4 p0[2], p1[2];
    float rsum[2], n2v[2];
    #pragma unroll
    for (int rr = 0; rr < 2; ++rr) {
        int i = ib * 2 + rr;
        int base = i * E_DIM + h * DH + c4;
        p0[rr] = *(const float4*)&g_Op[0][base];
        p1[rr] = *(const float4*)&g_Op[1][base];
        rsum[rr] = g_rsp[0][h][i] + g_rsp[1][h][i];
        n2v[rr]  = g_n2[h][i];
    }
    float4 gl = *(const float4*)&lnsc[h * DH + c4];

    float x[2][4], s[2], s2[2];
    #pragma unroll
    for (int rr = 0; rr < 2; ++rr) {
        float denom = fmaxf(fabsf(rsum[rr]), n2v[rr]) + EPS_F;
        float invd = 1.f / denom;
        x[rr][0] = (p0[rr].x + p1[rr].x) * invd;
        x[rr][1] = (p0[rr].y + p1[rr].y) * invd;
        x[rr][2] = (p0[rr].z + p1[rr].z) * invd;
        x[rr][3] = (p0[rr].w + p1[rr].w) * invd;
        s[rr]  = x[rr][0] + x[rr][1] + x[rr][2] + x[rr][3];
        s2[rr] = x[rr][0] * x[rr][0] + x[rr][1] * x[rr][1]
               + x[rr][2] * x[rr][2] + x[rr][3] * x[rr][3];
    }
    #pragma unroll
    for (int o = 16; o > 0; o >>= 1) {
        #pragma unroll
        for (int rr = 0; rr < 2; ++rr) {
            s[rr]  += __shfl_xor_sync(0xffffffffu, s[rr],  o);
            s2[rr] += __shfl_xor_sync(0xffffffffu, s2[rr], o);
        }
    }
    #pragma unroll
    for (int rr = 0; rr < 2; ++rr) {
        float mean = s[rr] * (1.f / 128.f);
        float rstd = rsqrtf(s2[rr] * (1.f / 128.f) - mean * mean + EPS_F);
        int base = (ib * 2 + rr) * E_DIM + h * DH + c4;
        float4 o4;
        o4.x = (x[rr][0] - mean) * rstd * gl.x;
        o4.y = (x[rr][1] - mean) * rstd * gl.y;
        o4.z = (x[rr][2] - mean) * rstd * gl.z;
        o4.w = (x[rr][3] - mean) * rstd * gl.w;
        *(float4*)&out[base] = o4;
    }
}

// =================================================================
extern "C" void kernel_launch(void* const* d_in, const int* in_sizes, int n_in,
                              void* d_out, int out_size) {
    const float* q    = (const float*)d_in[0];
    const float* k    = (const float*)d_in[1];
    const float* v    = (const float*)d_in[2];
    const float* Wi   = (const float*)d_in[3];
    const float* bi   = (const float*)d_in[4];
    const float* Wf   = (const float*)d_in[5];
    const float* bf   = (const float*)d_in[6];
    const float* lnsc = (const float*)d_in[7];
    float* out = (float*)d_out;

    const int gate_smem = (512 * 16 + 8 * 16 * 33 + 8 * 32 * 20) * 4;  // 70144 B
    const int attn_smem = 4 * 128 * STH * 2 + 768 * 4;                 // 142336 B

    cudaFuncSetAttribute(gate_kernel, cudaFuncAttributeMaxDynamicSharedMemorySize, gate_smem);
    cudaFuncSetAttribute(attn_kernel, cudaFuncAttributeMaxDynamicSharedMemorySize, attn_smem);

    gate_kernel<<<dim3(128, 6), 256, gate_smem>>>(q, k, v, Wi, Wf);
    scan_kernel<<<8, 1024>>>(bi, bf);
    attn_kernel<<<dim3(16, NH), 512, attn_smem>>>(q, k, v);
    fixup_kernel<<<S_LEN / 2, 256>>>(lnsc, out);
}

// round 9
// speedup vs baseline: 1.3063x; 1.0136x over previous
#include <cuda_runtime.h>
#include <cuda_fp16.h>
#include <math.h>

#define S_LEN 2048
#define E_DIM 1024
#define NH    8
#define DH    128
#define EPS_F 1e-6f

// ---------------- scratch ----------------
__device__ float g_part[3][16][S_LEN];  // gate partials: slice, gate(0-7 i, 8-15 f), s
__device__ float g_M [NH][S_LEN];       // prefix max of a[j] = i_pre - cum
__device__ float g_n2[NH][S_LEN];       // exp(-(cum+M))
__device__ float g_E [NH][S_LEN];       // exp(a[j] - T_tile(j))
__device__ float g_T [NH][S_LEN/128];   // per-128-tile max of a
__device__ float g_Op[2][S_LEN * E_DIM];// partial O (unnormalized), per j-half
__device__ float g_rsp[2][NH][S_LEN];   // partial rowsums, per j-half

__device__ __forceinline__ void mma16(float* d, const unsigned* a, const unsigned* b) {
    asm volatile("mma.sync.aligned.m16n8k16.row.col.f32.f16.f16.f32 "
        "{%0,%1,%2,%3}, {%4,%5,%6,%7}, {%8,%9}, {%0,%1,%2,%3};"
        : "+f"(d[0]), "+f"(d[1]), "+f"(d[2]), "+f"(d[3])
        : "r"(a[0]), "r"(a[1]), "r"(a[2]), "r"(a[3]), "r"(b[0]), "r"(b[1]));
}
__device__ __forceinline__ void ldsm4t(unsigned* r, unsigned addr) {
    asm volatile("ldmatrix.sync.aligned.m8n8.x4.trans.shared.b16 {%0,%1,%2,%3}, [%4];"
        : "=r"(r[0]), "=r"(r[1]), "=r"(r[2]), "=r"(r[3]) : "r"(addr));
}

// =================================================================
// Kernel 1: gate partials v4 — 128B in flight per thread.
// grid (64, 3) x 256 thr, 2 CTA/SM. CTA = 32 rows x one 1024-e slice.
// Warp owns 128 e in 4 chunks of 32e; prefetch 8 float4 (4 KB/warp)
// while computing. Compute: lane = row, 32e x 16 gates per chunk.
// =================================================================
__global__ void __launch_bounds__(256, 2)
gate_kernel(const float* __restrict__ q,
            const float* __restrict__ k,
            const float* __restrict__ v,
            const float* __restrict__ Wi,
            const float* __restrict__ Wf) {
    extern __shared__ float gs[];
    float* sW  = gs;                  // [1024][16] = 65536 B
    float* sX  = sW + 1024 * 16;      // per warp [32][33]; 8 warps = 8448 floats
    float* red = sX;                  // UNION: reused after compute (sync'd)

    int tid = threadIdx.x, w = tid >> 5, lane = tid & 31;
    int sl = blockIdx.y;
    const float* x = (sl == 0) ? q : (sl == 1) ? k : v;

    for (int i = tid; i < 1024 * 8; i += 256) {
        int e = i >> 3, g = i & 7;
        sW[e * 16 + g]     = Wi[(sl * 1024 + e) * 8 + g];
        sW[e * 16 + 8 + g] = Wf[(sl * 1024 + e) * 8 + g];
    }
    __syncthreads();

    int r0 = blockIdx.x * 32;
    int e_off = w * 128;
    int lr = lane >> 3, cq = (lane & 7) * 4;
    const float* xb = x + r0 * E_DIM + e_off;
    float* sXw = sX + w * (32 * 33);

    float acc[16];
    #pragma unroll
    for (int g = 0; g < 16; ++g) acc[g] = 0.f;

    float4 buf[8];
    #pragma unroll
    for (int i = 0; i < 8; ++i)
        buf[i] = *(const float4*)&xb[(lr + 4 * i) * E_DIM + cq];

    #pragma unroll
    for (int c = 0; c < 4; ++c) {
        __syncwarp();
        #pragma unroll
        for (int i = 0; i < 8; ++i) {
            int row = lr + 4 * i;
            sXw[row * 33 + cq + 0] = buf[i].x;
            sXw[row * 33 + cq + 1] = buf[i].y;
            sXw[row * 33 + cq + 2] = buf[i].z;
            sXw[row * 33 + cq + 3] = buf[i].w;
        }
        __syncwarp();
        if (c < 3) {
            #pragma unroll
            for (int i = 0; i < 8; ++i)
                buf[i] = *(const float4*)&xb[(lr + 4 * i) * E_DIM + (c + 1) * 32 + cq];
        }
        int eb = e_off + c * 32;
        #pragma unroll 8
        for (int e2 = 0; e2 < 32; ++e2) {
            float xv = sXw[lane * 33 + e2];            // lane = row
            const float4 w0 = *(const float4*)&sW[(eb + e2) * 16 + 0];
            const float4 w1 = *(const float4*)&sW[(eb + e2) * 16 + 4];
            const float4 w2 = *(const float4*)&sW[(eb + e2) * 16 + 8];
            const float4 w3 = *(const float4*)&sW[(eb + e2) * 16 + 12];
            acc[0]  += xv * w0.x;  acc[1]  += xv * w0.y;
            acc[2]  += xv * w0.z;  acc[3]  += xv * w0.w;
            acc[4]  += xv * w1.x;  acc[5]  += xv * w1.y;
            acc[6]  += xv * w1.z;  acc[7]  += xv * w1.w;
            acc[8]  += xv * w2.x;  acc[9]  += xv * w2.y;
            acc[10] += xv * w2.z;  acc[11] += xv * w2.w;
            acc[12] += xv * w3.x;  acc[13] += xv * w3.y;
            acc[14] += xv * w3.z;  acc[15] += xv * w3.w;
        }
    }

    __syncthreads();     // all compute reads of sX done before red reuse
    float* rw = red + (w * 32 + lane) * 20;
    *(float4*)&rw[0]  = make_float4(acc[0],  acc[1],  acc[2],  acc[3]);
    *(float4*)&rw[4]  = make_float4(acc[4],  acc[5],  acc[6],  acc[7]);
    *(float4*)&rw[8]  = make_float4(acc[8],  acc[9],  acc[10], acc[11]);
    *(float4*)&rw[12] = make_float4(acc[12], acc[13], acc[14], acc[15]);
    __syncthreads();
    #pragma unroll
    for (int o = tid; o < 512; o += 256) {
        int row = o >> 4, g = o & 15;        // 32 rows x 16 gates
        float s = 0.f;
        #pragma unroll
        for (int w8 = 0; w8 < 8; ++w8)
            s += red[(w8 * 32 + row) * 20 + g];
        g_part[sl][g][r0 + row] = s;
    }
}

// =================================================================
// Kernel 2: reduce 3 partials + bias, shuffle scans, tile max, E.
// =================================================================
__device__ __forceinline__ float lsig(float x) {
    float m = fminf(x, 0.f);
    return m - log1pf(expf(-fabsf(x)));
}

__global__ void scan_kernel(const float* __restrict__ bi_p,
                            const float* __restrict__ bf_p) {
    int h = blockIdx.x;
    int t = threadIdx.x;
    int lane = t & 31, wid = t >> 5;
    __shared__ float wsum[32], wmax[32], tmax[32];

    float bi = bi_p[h], bf = bf_p[h];
    float i0 = bi, i1 = bi, f0 = bf, f1 = bf;
    #pragma unroll
    for (int sl = 0; sl < 3; ++sl) {
        float2 vi = *(const float2*)&g_part[sl][h][2 * t];
        float2 vf = *(const float2*)&g_part[sl][h + 8][2 * t];
        i0 += vi.x; i1 += vi.y; f0 += vf.x; f1 += vf.y;
    }
    float l0 = lsig(f0), l1 = lsig(f1);

    float inc = l0 + l1;
    #pragma unroll
    for (int o = 1; o < 32; o <<= 1) {
        float n = __shfl_up_sync(0xffffffffu, inc, o);
        if (lane >= o) inc += n;
    }
    if (lane == 31) wsum[wid] = inc;
    __syncthreads();
    if (t < 32) {
        float v2 = wsum[t];
        #pragma unroll
        for (int o = 1; o < 32; o <<= 1) {
            float n = __shfl_up_sync(0xffffffffu, v2, o);
            if (t >= o) v2 += n;
        }
        wsum[t] = v2;
    }
    __syncthreads();
    float base = wid ? wsum[wid - 1] : 0.f;
    float cum1 = base + inc;
    float cum0 = cum1 - l1;

    float a0 = i0 - cum0, a1 = i1 - cum1;

    float pm = fmaxf(a0, a1);
    float incm = pm;
    #pragma unroll
    for (int o = 1; o < 32; o <<= 1) {
        float n = __shfl_up_sync(0xffffffffu, incm, o);
        if (lane >= o) incm = fmaxf(incm, n);
    }
    if (lane == 31) wmax[wid] = incm;
    __syncthreads();
    if (t < 32) {
        float v2 = wmax[t];
        #pragma unroll
        for (int o = 1; o < 32; o <<= 1) {
            float n = __shfl_up_sync(0xffffffffu, v2, o);
            if (t >= o) v2 = fmaxf(v2, n);
        }
        wmax[t] = v2;
    }
    __syncthreads();
    float basem = wid ? wmax[wid - 1] : -3.4e38f;
    float prev  = __shfl_up_sync(0xffffffffu, incm, 1);
    float exw   = lane ? prev : -3.4e38f;
    float M0 = fmaxf(fmaxf(basem, exw), a0);
    float M1 = fmaxf(M0, a1);
    g_M[h][2 * t]      = M0;
    g_M[h][2 * t + 1]  = M1;
    g_n2[h][2 * t]     = expf(-(cum0 + M0));
    g_n2[h][2 * t + 1] = expf(-(cum1 + M1));

    float mx = pm;
    #pragma unroll
    for (int off = 16; off > 0; off >>= 1)
        mx = fmaxf(mx, __shfl_xor_sync(0xffffffffu, mx, off));
    if (lane == 0) tmax[wid] = mx;
    __syncthreads();
    float T = fmaxf(tmax[wid & ~1], tmax[wid | 1]);
    if ((wid & 1) == 0 && lane == 0) g_T[h][wid >> 1] = T;
    g_E[h][2 * t]     = expf(a0 - T);
    g_E[h][2 * t + 1] = expf(a1 - T);
}

// =================================================================
// Kernel 3: fp16 TC attention, BM=128, split-j balanced (R6, unchanged).
// =================================================================
#define STH 136

__global__ void __launch_bounds__(512, 1)
attn_kernel(const float* __restrict__ q,
            const float* __restrict__ k,
            const float* __restrict__ v) {
    extern __shared__ __half smem_h[];
    __half* Qs = smem_h;                   // [128][STH]
    __half* Ks = Qs + 128 * STH;
    __half* Vs = Ks + 128 * STH;
    __half* Ps = Vs + 128 * STH;
    float* sMq = (float*)(Ps + 128 * STH); // [128]
    float* sR  = sMq + 128;                // [128]
    float* rrs = sR + 128;                 // [4][128]

    int h    = blockIdx.y;
    int ib   = blockIdx.x;                 // 0..15
    int tid  = threadIdx.x;
    int wid  = tid >> 5, lane = tid & 31;
    int wy   = wid >> 2, wx = wid & 3;
    int g    = lane >> 2, tig = lane & 3;

    unsigned vsm = (unsigned)__cvta_generic_to_shared(Vs);
    {
        int sel = lane >> 3, l8 = lane & 7;
        vsm += (((sel & 1) * 8 + l8) * STH + wx * 32 + (sel >> 1) * 8) * 2;
    }

    const float qscale = 0.08838834764831845f;   // 1/sqrt(128)

    #pragma unroll 1
    for (int it = 0; it < 2; ++it) {
        int qt   = it ? ib : (15 - ib);
        int half = it ? 0 : 1;
        int nj   = qt + 1;
        int jlo  = half ? (nj >> 1) : 0;
        int jhi  = half ? nj : (nj >> 1);
        int i0   = qt * 128;

        __syncthreads();
        for (int idx = tid; idx < 128 * 32; idx += 512) {
            int i = idx >> 5, c4 = (idx & 31) * 4;
            float4 t4 = *(const float4*)&q[(i0 + i) * E_DIM + h * DH + c4];
            __half2 h01 = __floats2half2_rn(t4.x * qscale, t4.y * qscale);
            __half2 h23 = __floats2half2_rn(t4.z * qscale, t4.w * qscale);
            *(uint2*)&Qs[i * STH + c4] = make_uint2(*(unsigned*)&h01, *(unsigned*)&h23);
        }
        if (tid < 128) sMq[tid] = g_M[h][i0 + tid];

        float Oa[2][4][4];
        #pragma unroll
        for (int mi = 0; mi < 2; ++mi)
            #pragma unroll
            for (int nt = 0; nt < 4; ++nt)
                #pragma unroll
                for (int c = 0; c < 4; ++c) Oa[mi][nt][c] = 0.f;
        float rs[2][2] = {{0.f, 0.f}, {0.f, 0.f}};
        __syncthreads();

        for (int jt = jlo; jt < jhi; ++jt) {
            int j0 = jt * 128;
            float T = g_T[h][jt];
            for (int idx = tid; idx < 128 * 32; idx += 512) {
                int j = idx >> 5, c4 = (idx & 31) * 4;
                float e = g_E[h][j0 + j];
                float4 kt = *(const float4*)&k[(j0 + j) * E_DIM + h * DH + c4];
                __half2 k01 = __floats2half2_rn(kt.x * e, kt.y * e);
                __half2 k23 = __floats2half2_rn(kt.z * e, kt.w * e);
                *(uint2*)&Ks[j * STH + c4] = make_uint2(*(unsigned*)&k01, *(unsigned*)&k23);
                float4 vt = *(const float4*)&v[(j0 + j) * E_DIM + h * DH + c4];
                __half2 v01 = __floats2half2_rn(vt.x, vt.y);
                __half2 v23 = __floats2half2_rn(vt.z, vt.w);
                *(uint2*)&Vs[j * STH + c4] = make_uint2(*(unsigned*)&v01, *(unsigned*)&v23);
            }
            if (tid < 128) sR[tid] = __expf(T - sMq[tid]);
            __syncthreads();

            // ---- QK^T ----
            float acc[2][4][4];
            #pragma unroll
            for (int mi = 0; mi < 2; ++mi)
                #pragma unroll
                for (int nt = 0; nt < 4; ++nt)
                    #pragma unroll
                    for (int c = 0; c < 4; ++c) acc[mi][nt][c] = 0.f;

            #pragma unroll
            for (int ks = 0; ks < 8; ++ks) {
                int d0 = ks * 16;
                unsigned a[2][4], b[4][2];
                #pragma unroll
                for (int mi = 0; mi < 2; ++mi) {
                    int r0 = wy * 32 + mi * 16 + g;
                    a[mi][0] = *(const unsigned*)&Qs[r0 * STH + d0 + 2 * tig];
                    a[mi][1] = *(const unsigned*)&Qs[(r0 + 8) * STH + d0 + 2 * tig];
                    a[mi][2] = *(const unsigned*)&Qs[r0 * STH + d0 + 8 + 2 * tig];
                    a[mi][3] = *(const unsigned*)&Qs[(r0 + 8) * STH + d0 + 8 + 2 * tig];
                }
                #pragma unroll
                for (int nt = 0; nt < 4; ++nt) {
                    int jb = wx * 32 + nt * 8 + g;
                    b[nt][0] = *(const unsigned*)&Ks[jb * STH + d0 + 2 * tig];
                    b[nt][1] = *(const unsigned*)&Ks[jb * STH + d0 + 8 + 2 * tig];
                }
                #pragma unroll
                for (int mi = 0; mi < 2; ++mi)
                    #pragma unroll
                    for (int nt = 0; nt < 4; ++nt)
                        mma16(acc[mi][nt], a[mi], b[nt]);
            }

            // ---- apply R, mask, rowsum, stage P ----
            bool diag = (jt == qt);
            #pragma unroll
            for (int mi = 0; mi < 2; ++mi) {
                int rl = wy * 32 + mi * 16 + g;
                float Rl = sR[rl], Rh = sR[rl + 8];
                int iglo = i0 + rl, ighi = iglo + 8;
                #pragma unroll
                for (int nt = 0; nt < 4; ++nt) {
                    int jc = wx * 32 + nt * 8 + 2 * tig;
                    int jg = j0 + jc;
                    float p0 = acc[mi][nt][0] * Rl;
                    float p1 = acc[mi][nt][1] * Rl;
                    float p2 = acc[mi][nt][2] * Rh;
                    float p3 = acc[mi][nt][3] * Rh;
                    if (diag) {
                        if (jg     > iglo) p0 = 0.f;
                        if (jg + 1 > iglo) p1 = 0.f;
                        if (jg     > ighi) p2 = 0.f;
                        if (jg + 1 > ighi) p3 = 0.f;
                    }
                    rs[mi][0] += p0 + p1;
                    rs[mi][1] += p2 + p3;
                    *(__half2*)&Ps[rl * STH + jc]       = __floats2half2_rn(p0, p1);
                    *(__half2*)&Ps[(rl + 8) * STH + jc] = __floats2half2_rn(p2, p3);
                }
            }
            __syncthreads();

            // ---- P @ V ----
            #pragma unroll
            for (int ks = 0; ks < 8; ++ks) {
                int j8 = ks * 16;
                unsigned a[2][4], b[4][2];
                #pragma unroll
                for (int mi = 0; mi < 2; ++mi) {
                    int r0 = wy * 32 + mi * 16 + g;
                    a[mi][0] = *(const unsigned*)&Ps[r0 * STH + j8 + 2 * tig];
                    a[mi][1] = *(const unsigned*)&Ps[(r0 + 8) * STH + j8 + 2 * tig];
                    a[mi][2] = *(const unsigned*)&Ps[r0 * STH + j8 + 8 + 2 * tig];
                    a[mi][3] = *(const unsigned*)&Ps[(r0 + 8) * STH + j8 + 8 + 2 * tig];
                }
                #pragma unroll
                for (int p = 0; p < 2; ++p) {
                    unsigned r4[4];
                    ldsm4t(r4, vsm + (unsigned)((j8 * STH + p * 16) * 2));
                    b[2 * p][0]     = r4[0];
                    b[2 * p][1]     = r4[1];
                    b[2 * p + 1][0] = r4[2];
                    b[2 * p + 1][1] = r4[3];
                }
                #pragma unroll
                for (int mi = 0; mi < 2; ++mi)
                    #pragma unroll
                    for (int nt = 0; nt < 4; ++nt)
                        mma16(Oa[mi][nt], a[mi], b[nt]);
            }
            __syncthreads();
        }

        // ---- epilogue: partial rowsums + partial O to global ----
        #pragma unroll
        for (int mi = 0; mi < 2; ++mi)
            #pragma unroll
            for (int c = 0; c < 2; ++c) {
                rs[mi][c] += __shfl_xor_sync(0xffffffffu, rs[mi][c], 1);
                rs[mi][c] += __shfl_xor_sync(0xffffffffu, rs[mi][c], 2);
            }
        if (tig == 0) {
            #pragma unroll
            for (int mi = 0; mi < 2; ++mi)
                #pragma unroll
                for (int c = 0; c < 2; ++c) {
                    int row = wy * 32 + mi * 16 + g + 8 * c;
                    rrs[wx * 128 + row] = rs[mi][c];
                }
        }
        __syncthreads();
        if (tid < 128) {
            float tot = rrs[tid] + rrs[128 + tid] + rrs[256 + tid] + rrs[384 + tid];
            g_rsp[half][h][i0 + tid] = tot;
        }
        float* Op = g_Op[half];
        #pragma unroll
        for (int mi = 0; mi < 2; ++mi)
            #pragma unroll
            for (int c = 0; c < 2; ++c) {
                int row = wy * 32 + mi * 16 + g + 8 * c;
                int grow = i0 + row;
                #pragma unroll
                for (int nt = 0; nt < 4; ++nt) {
                    *(float2*)&Op[grow * E_DIM + h * DH + wx * 32 + nt * 8 + 2 * tig]
                        = make_float2(Oa[mi][nt][2 * c], Oa[mi][nt][2 * c + 1]);
                }
            }
    }
}

// =================================================================
// Kernel 4: fixup — 4 rows per block (R7 best). grid 512 x 256 thr.
// =================================================================
__global__ void fixup_kernel(const float* __restrict__ lnsc,
                             float* __restrict__ out) {
    int ib = blockIdx.x;
    int h = threadIdx.x >> 5, lane = threadIdx.x & 31;
    int c4 = lane * 4;

    float4 p0[4], p1[4];
    float rsum[4], n2v[4];
    #pragma unroll
    for (int rr = 0; rr < 4; ++rr) {
        int i = ib * 4 + rr;
        int base = i * E_DIM + h * DH + c4;
        p0[rr] = *(const float4*)&g_Op[0][base];
        p1[rr] = *(const float4*)&g_Op[1][base];
        rsum[rr] = g_rsp[0][h][i] + g_rsp[1][h][i];
        n2v[rr]  = g_n2[h][i];
    }
    float4 gl = *(const float4*)&lnsc[h * DH + c4];

    float x[4][4], s[4], s2[4];
    #pragma unroll
    for (int rr = 0; rr < 4; ++rr) {
        float denom = fmaxf(fabsf(rsum[rr]), n2v[rr]) + EPS_F;
        float invd = 1.f / denom;
        x[rr][0] = (p0[rr].x + p1[rr].x) * invd;
        x[rr][1] = (p0[rr].y + p1[rr].y) * invd;
        x[rr][2] = (p0[rr].z + p1[rr].z) * invd;
        x[rr][3] = (p0[rr].w + p1[rr].w) * invd;
        s[rr]  = x[rr][0] + x[rr][1] + x[rr][2] + x[rr][3];
        s2[rr] = x[rr][0] * x[rr][0] + x[rr][1] * x[rr][1]
               + x[rr][2] * x[rr][2] + x[rr][3] * x[rr][3];
    }
    #pragma unroll
    for (int o = 16; o > 0; o >>= 1) {
        #pragma unroll
        for (int rr = 0; rr < 4; ++rr) {
            s[rr]  += __shfl_xor_sync(0xffffffffu, s[rr],  o);
            s2[rr] += __shfl_xor_sync(0xffffffffu, s2[rr], o);
        }
    }
    #pragma unroll
    for (int rr = 0; rr < 4; ++rr) {
        float mean = s[rr] * (1.f / 128.f);
        float rstd = rsqrtf(s2[rr] * (1.f / 128.f) - mean * mean + EPS_F);
        int base = (ib * 4 + rr) * E_DIM + h * DH + c4;
        float4 o4;
        o4.x = (x[rr][0] - mean) * rstd * gl.x;
        o4.y = (x[rr][1] - mean) * rstd * gl.y;
        o4.z = (x[rr][2] - mean) * rstd * gl.z;
        o4.w = (x[rr][3] - mean) * rstd * gl.w;
        *(float4*)&out[base] = o4;
    }
}

// =================================================================
extern "C" void kernel_launch(void* const* d_in, const int* in_sizes, int n_in,
                              void* d_out, int out_size) {
    const float* q    = (const float*)d_in[0];
    const float* k    = (const float*)d_in[1];
    const float* v    = (const float*)d_in[2];
    const float* Wi   = (const float*)d_in[3];
    const float* bi   = (const float*)d_in[4];
    const float* Wf   = (const float*)d_in[5];
    const float* bf   = (const float*)d_in[6];
    const float* lnsc = (const float*)d_in[7];
    float* out = (float*)d_out;

    const int gate_smem = (1024 * 16 + 8 * 32 * 33) * 4;   // 99328 B
    const int attn_smem = 4 * 128 * STH * 2 + 768 * 4;     // 142336 B

    cudaFuncSetAttribute(gate_kernel, cudaFuncAttributeMaxDynamicSharedMemorySize, gate_smem);
    cudaFuncSetAttribute(attn_kernel, cudaFuncAttributeMaxDynamicSharedMemorySize, attn_smem);

    gate_kernel<<<dim3(64, 3), 256, gate_smem>>>(q, k, v, Wi, Wf);
    scan_kernel<<<8, 1024>>>(bi, bf);
    attn_kernel<<<dim3(16, NH), 512, attn_smem>>>(q, k, v);
    fixup_kernel<<<S_LEN / 4, 256>>>(lnsc, out);
}

// round 10
// speedup vs baseline: 1.3540x; 1.0365x over previous
#include <cuda_runtime.h>
#include <cuda_fp16.h>
#include <math.h>

#define S_LEN 2048
#define E_DIM 1024
#define NH    8
#define DH    128
#define EPS_F 1e-6f

// ---------------- scratch ----------------
__device__ float g_part[3][16][S_LEN];  // gate partials: slice, gate(0-7 i, 8-15 f), s
__device__ float g_M [NH][S_LEN];       // prefix max of a[j] = i_pre - cum
__device__ float g_n2[NH][S_LEN];       // exp(-(cum+M))
__device__ float g_E [NH][S_LEN];       // exp(a[j] - T_tile(j))
__device__ float g_T [NH][S_LEN/128];   // per-128-tile max of a
__device__ float g_Op[2][S_LEN * E_DIM];// partial O (unnormalized), per j-half
__device__ float g_rsp[2][NH][S_LEN];   // partial rowsums, per j-half
__device__ __half g_kh[S_LEN * E_DIM];  // fp16 K with E folded in
__device__ __half g_vh[S_LEN * E_DIM];  // fp16 V

__device__ __forceinline__ void mma16(float* d, const unsigned* a, const unsigned* b) {
    asm volatile("mma.sync.aligned.m16n8k16.row.col.f32.f16.f16.f32 "
        "{%0,%1,%2,%3}, {%4,%5,%6,%7}, {%8,%9}, {%0,%1,%2,%3};"
        : "+f"(d[0]), "+f"(d[1]), "+f"(d[2]), "+f"(d[3])
        : "r"(a[0]), "r"(a[1]), "r"(a[2]), "r"(a[3]), "r"(b[0]), "r"(b[1]));
}
__device__ __forceinline__ void ldsm4t(unsigned* r, unsigned addr) {
    asm volatile("ldmatrix.sync.aligned.m8n8.x4.trans.shared.b16 {%0,%1,%2,%3}, [%4];"
        : "=r"(r[0]), "=r"(r[1]), "=r"(r[2]), "=r"(r[3]) : "r"(addr));
}
__device__ __forceinline__ void cpa16(unsigned dst, const __half* src) {
    asm volatile("cp.async.cg.shared.global [%0], [%1], 16;" :: "r"(dst), "l"(src));
}
__device__ __forceinline__ void cpa_commit() {
    asm volatile("cp.async.commit_group;");
}
template<int N> __device__ __forceinline__ void cpa_wait() {
    asm volatile("cp.async.wait_group %0;" :: "n"(N));
}

// =================================================================
// Kernel 1: gate partials (exact R6 variant — best measured).
// grid (128, 3) x 256 thr, 2 CTA/SM. CTA = 16 rows x one 1024-e slice.
// =================================================================
__global__ void __launch_bounds__(256, 2)
gate_kernel(const float* __restrict__ q,
            const float* __restrict__ k,
            const float* __restrict__ v,
            const float* __restrict__ Wi,
            const float* __restrict__ Wf) {
    extern __shared__ float gs[];
    float* sW  = gs;                  // [1024][16]
    float* sX  = sW + 1024 * 16;      // per warp [16][33]
    float* red = sX + 8 * 16 * 33;    // [8*32][20]

    int tid = threadIdx.x, w = tid >> 5, lane = tid & 31;
    int sl = blockIdx.y;
    const float* x = (sl == 0) ? q : (sl == 1) ? k : v;

    for (int i = tid; i < 1024 * 8; i += 256) {
        int e = i >> 3, g = i & 7;
        sW[e * 16 + g]     = Wi[(sl * 1024 + e) * 8 + g];
        sW[e * 16 + 8 + g] = Wf[(sl * 1024 + e) * 8 + g];
    }
    __syncthreads();

    int r0 = blockIdx.x * 16;
    int e_off = w * 128;
    int rr = lane & 15, hh = lane >> 4;
    const float* xb = x + r0 * E_DIM + e_off;
    float* sXw = sX + w * 16 * 33;

    float acc[16];
    #pragma unroll
    for (int g = 0; g < 16; ++g) acc[g] = 0.f;

    float buf[16];
    #pragma unroll
    for (int r = 0; r < 16; ++r) buf[r] = xb[r * E_DIM + lane];

    #pragma unroll
    for (int c = 0; c < 4; ++c) {
        __syncwarp();
        #pragma unroll
        for (int r = 0; r < 16; ++r) sXw[r * 33 + lane] = buf[r];
        __syncwarp();
        if (c < 3) {
            #pragma unroll
            for (int r = 0; r < 16; ++r)
                buf[r] = xb[r * E_DIM + (c + 1) * 32 + lane];
        }
        int eb = e_off + c * 32 + hh * 16;
        #pragma unroll
        for (int e2 = 0; e2 < 16; ++e2) {
            float xv = sXw[rr * 33 + hh * 16 + e2];
            const float4 w0 = *(const float4*)&sW[(eb + e2) * 16 + 0];
            const float4 w1 = *(const float4*)&sW[(eb + e2) * 16 + 4];
            const float4 w2 = *(const float4*)&sW[(eb + e2) * 16 + 8];
            const float4 w3 = *(const float4*)&sW[(eb + e2) * 16 + 12];
            acc[0]  += xv * w0.x;  acc[1]  += xv * w0.y;
            acc[2]  += xv * w0.z;  acc[3]  += xv * w0.w;
            acc[4]  += xv * w1.x;  acc[5]  += xv * w1.y;
            acc[6]  += xv * w1.z;  acc[7]  += xv * w1.w;
            acc[8]  += xv * w2.x;  acc[9]  += xv * w2.y;
            acc[10] += xv * w2.z;  acc[11] += xv * w2.w;
            acc[12] += xv * w3.x;  acc[13] += xv * w3.y;
            acc[14] += xv * w3.z;  acc[15] += xv * w3.w;
        }
    }

    __syncthreads();
    float* rw = red + (w * 32 + lane) * 20;
    *(float4*)&rw[0]  = make_float4(acc[0],  acc[1],  acc[2],  acc[3]);
    *(float4*)&rw[4]  = make_float4(acc[4],  acc[5],  acc[6],  acc[7]);
    *(float4*)&rw[8]  = make_float4(acc[8],  acc[9],  acc[10], acc[11]);
    *(float4*)&rw[12] = make_float4(acc[12], acc[13], acc[14], acc[15]);
    __syncthreads();
    {
        int row = tid >> 4, g = tid & 15;
        float s = 0.f;
        #pragma unroll
        for (int w8 = 0; w8 < 8; ++w8)
            s += red[(w8 * 32 + row) * 20 + g] + red[(w8 * 32 + 16 + row) * 20 + g];
        g_part[sl][g][r0 + row] = s;
    }
}

// =================================================================
// Kernel 2: reduce 3 partials + bias, shuffle scans, tile max, E.
// =================================================================
__device__ __forceinline__ float lsig(float x) {
    float m = fminf(x, 0.f);
    return m - log1pf(expf(-fabsf(x)));
}

__global__ void scan_kernel(const float* __restrict__ bi_p,
                            const float* __restrict__ bf_p) {
    int h = blockIdx.x;
    int t = threadIdx.x;
    int lane = t & 31, wid = t >> 5;
    __shared__ float wsum[32], wmax[32], tmax[32];

    float bi = bi_p[h], bf = bf_p[h];
    float i0 = bi, i1 = bi, f0 = bf, f1 = bf;
    #pragma unroll
    for (int sl = 0; sl < 3; ++sl) {
        float2 vi = *(const float2*)&g_part[sl][h][2 * t];
        float2 vf = *(const float2*)&g_part[sl][h + 8][2 * t];
        i0 += vi.x; i1 += vi.y; f0 += vf.x; f1 += vf.y;
    }
    float l0 = lsig(f0), l1 = lsig(f1);

    float inc = l0 + l1;
    #pragma unroll
    for (int o = 1; o < 32; o <<= 1) {
        float n = __shfl_up_sync(0xffffffffu, inc, o);
        if (lane >= o) inc += n;
    }
    if (lane == 31) wsum[wid] = inc;
    __syncthreads();
    if (t < 32) {
        float v2 = wsum[t];
        #pragma unroll
        for (int o = 1; o < 32; o <<= 1) {
            float n = __shfl_up_sync(0xffffffffu, v2, o);
            if (t >= o) v2 += n;
        }
        wsum[t] = v2;
    }
    __syncthreads();
    float base = wid ? wsum[wid - 1] : 0.f;
    float cum1 = base + inc;
    float cum0 = cum1 - l1;

    float a0 = i0 - cum0, a1 = i1 - cum1;

    float pm = fmaxf(a0, a1);
    float incm = pm;
    #pragma unroll
    for (int o = 1; o < 32; o <<= 1) {
        float n = __shfl_up_sync(0xffffffffu, incm, o);
        if (lane >= o) incm = fmaxf(incm, n);
    }
    if (lane == 31) wmax[wid] = incm;
    __syncthreads();
    if (t < 32) {
        float v2 = wmax[t];
        #pragma unroll
        for (int o = 1; o < 32; o <<= 1) {
            float n = __shfl_up_sync(0xffffffffu, v2, o);
            if (t >= o) v2 = fmaxf(v2, n);
        }
        wmax[t] = v2;
    }
    __syncthreads();
    float basem = wid ? wmax[wid - 1] : -3.4e38f;
    float prev  = __shfl_up_sync(0xffffffffu, incm, 1);
    float exw   = lane ? prev : -3.4e38f;
    float M0 = fmaxf(fmaxf(basem, exw), a0);
    float M1 = fmaxf(M0, a1);
    g_M[h][2 * t]      = M0;
    g_M[h][2 * t + 1]  = M1;
    g_n2[h][2 * t]     = expf(-(cum0 + M0));
    g_n2[h][2 * t + 1] = expf(-(cum1 + M1));

    float mx = pm;
    #pragma unroll
    for (int off = 16; off > 0; off >>= 1)
        mx = fmaxf(mx, __shfl_xor_sync(0xffffffffu, mx, off));
    if (lane == 0) tmax[wid] = mx;
    __syncthreads();
    float T = fmaxf(tmax[wid & ~1], tmax[wid | 1]);
    if ((wid & 1) == 0 && lane == 0) g_T[h][wid >> 1] = T;
    g_E[h][2 * t]     = expf(a0 - T);
    g_E[h][2 * t + 1] = expf(a1 - T);
}

// =================================================================
// Kernel 2.5: prepass — K*E and V to fp16. grid 256 x 256 thr.
// =================================================================
__global__ void prep_kernel(const float* __restrict__ k,
                            const float* __restrict__ v) {
    int tid = threadIdx.x;
    int c4 = tid * 4;
    int h = tid >> 5;
    int r0 = blockIdx.x * 8;
    #pragma unroll
    for (int rr = 0; rr < 8; ++rr) {
        int row = r0 + rr;
        float e = g_E[h][row];
        float4 k4 = *(const float4*)&k[row * E_DIM + c4];
        __half2 ka = __floats2half2_rn(k4.x * e, k4.y * e);
        __half2 kb = __floats2half2_rn(k4.z * e, k4.w * e);
        *(uint2*)&g_kh[row * E_DIM + c4] = make_uint2(*(unsigned*)&ka, *(unsigned*)&kb);
        float4 v4 = *(const float4*)&v[row * E_DIM + c4];
        __half2 va = __floats2half2_rn(v4.x, v4.y);
        __half2 vb = __floats2half2_rn(v4.z, v4.w);
        *(uint2*)&g_vh[row * E_DIM + c4] = make_uint2(*(unsigned*)&va, *(unsigned*)&vb);
    }
}

// =================================================================
// Kernel 3: fp16 TC attention, BM=128, split-j balanced,
// cp.async double-buffered K/V staging from fp16 prepass arrays.
// =================================================================
#define STH 136
#define TILE_HALFS (128 * STH)
#define TILE_BYTES (TILE_HALFS * 2)   // 34816

__global__ void __launch_bounds__(512, 1)
attn_kernel(const float* __restrict__ q) {
    extern __shared__ __half smem_h[];
    __half* Qs = smem_h;                     // [128][STH]
    __half* Kb = smem_h + TILE_HALFS;        // 2 buffers
    __half* Vb = smem_h + 3 * TILE_HALFS;    // 2 buffers
    __half* Ps = smem_h + 5 * TILE_HALFS;
    float* sMq = (float*)(smem_h + 6 * TILE_HALFS);  // [128]
    float* sR  = sMq + 128;                          // [128]
    float* rrs = sR + 128;                           // [4][128]

    int h    = blockIdx.y;
    int ib   = blockIdx.x;
    int tid  = threadIdx.x;
    int wid  = tid >> 5, lane = tid & 31;
    int wy   = wid >> 2, wx = wid & 3;
    int g    = lane >> 2, tig = lane & 3;

    unsigned kb_u32 = (unsigned)__cvta_generic_to_shared(Kb);
    unsigned vb_u32 = (unsigned)__cvta_generic_to_shared(Vb);
    unsigned vsm_lane;
    {
        int sel = lane >> 3, l8 = lane & 7;
        vsm_lane = (unsigned)((((sel & 1) * 8 + l8) * STH + wx * 32 + (sel >> 1) * 8) * 2);
    }

    const float qscale = 0.08838834764831845f;   // 1/sqrt(128)

    #pragma unroll 1
    for (int it = 0; it < 2; ++it) {
        int qt   = it ? ib : (15 - ib);
        int half = it ? 0 : 1;
        int nj   = qt + 1;
        int jlo  = half ? (nj >> 1) : 0;
        int jhi  = half ? nj : (nj >> 1);
        int i0   = qt * 128;

        __syncthreads();  // prior item done before smem reuse
        // stage Q (fp32 -> half, pre-scaled)
        for (int idx = tid; idx < 128 * 32; idx += 512) {
            int i = idx >> 5, c4 = (idx & 31) * 4;
            float4 t4 = *(const float4*)&q[(i0 + i) * E_DIM + h * DH + c4];
            __half2 h01 = __floats2half2_rn(t4.x * qscale, t4.y * qscale);
            __half2 h23 = __floats2half2_rn(t4.z * qscale, t4.w * qscale);
            *(uint2*)&Qs[i * STH + c4] = make_uint2(*(unsigned*)&h01, *(unsigned*)&h23);
        }
        if (tid < 128) sMq[tid] = g_M[h][i0 + tid];

        // issue first K/V tile (buffer 0)
        if (jlo < jhi) {
            const __half* ks = g_kh + (size_t)(jlo * 128) * E_DIM + h * DH;
            const __half* vs = g_vh + (size_t)(jlo * 128) * E_DIM + h * DH;
            #pragma unroll
            for (int t = 0; t < 4; ++t) {
                int chunk = tid + t * 512;
                int row = chunk >> 4, c16 = chunk & 15;
                cpa16(kb_u32 + row * 272 + c16 * 16, ks + row * E_DIM + c16 * 8);
                cpa16(vb_u32 + row * 272 + c16 * 16, vs + row * E_DIM + c16 * 8);
            }
            cpa_commit();
        }

        float Oa[2][4][4];
        #pragma unroll
        for (int mi = 0; mi < 2; ++mi)
            #pragma unroll
            for (int nt = 0; nt < 4; ++nt)
                #pragma unroll
                for (int c = 0; c < 4; ++c) Oa[mi][nt][c] = 0.f;
        float rs[2][2] = {{0.f, 0.f}, {0.f, 0.f}};

        int cur = 0;
        for (int jt = jlo; jt < jhi; ++jt) {
            int j0 = jt * 128;
            // prefetch next tile into other buffer, then wait for current
            if (jt + 1 < jhi) {
                int nb = cur ^ 1;
                const __half* ks = g_kh + (size_t)((jt + 1) * 128) * E_DIM + h * DH;
                const __half* vs = g_vh + (size_t)((jt + 1) * 128) * E_DIM + h * DH;
                #pragma unroll
                for (int t = 0; t < 4; ++t) {
                    int chunk = tid + t * 512;
                    int row = chunk >> 4, c16 = chunk & 15;
                    cpa16(kb_u32 + nb * TILE_BYTES + row * 272 + c16 * 16,
                          ks + row * E_DIM + c16 * 8);
                    cpa16(vb_u32 + nb * TILE_BYTES + row * 272 + c16 * 16,
                          vs + row * E_DIM + c16 * 8);
                }
                cpa_commit();
                cpa_wait<1>();
            } else {
                cpa_wait<0>();
            }
            if (tid < 128) sR[tid] = __expf(g_T[h][jt] - sMq[tid]);
            __syncthreads();

            const __half* Kc = Kb + cur * TILE_HALFS;

            // ---- QK^T ----
            float acc[2][4][4];
            #pragma unroll
            for (int mi = 0; mi < 2; ++mi)
                #pragma unroll
                for (int nt = 0; nt < 4; ++nt)
                    #pragma unroll
                    for (int c = 0; c < 4; ++c) acc[mi][nt][c] = 0.f;

            #pragma unroll
            for (int ks8 = 0; ks8 < 8; ++ks8) {
                int d0 = ks8 * 16;
                unsigned a[2][4], b[4][2];
                #pragma unroll
                for (int mi = 0; mi < 2; ++mi) {
                    int r0 = wy * 32 + mi * 16 + g;
                    a[mi][0] = *(const unsigned*)&Qs[r0 * STH + d0 + 2 * tig];
                    a[mi][1] = *(const unsigned*)&Qs[(r0 + 8) * STH + d0 + 2 * tig];
                    a[mi][2] = *(const unsigned*)&Qs[r0 * STH + d0 + 8 + 2 * tig];
                    a[mi][3] = *(const unsigned*)&Qs[(r0 + 8) * STH + d0 + 8 + 2 * tig];
                }
                #pragma unroll
                for (int nt = 0; nt < 4; ++nt) {
                    int jb = wx * 32 + nt * 8 + g;
                    b[nt][0] = *(const unsigned*)&Kc[jb * STH + d0 + 2 * tig];
                    b[nt][1] = *(const unsigned*)&Kc[jb * STH + d0 + 8 + 2 * tig];
                }
                #pragma unroll
                for (int mi = 0; mi < 2; ++mi)
                    #pragma unroll
                    for (int nt = 0; nt < 4; ++nt)
                        mma16(acc[mi][nt], a[mi], b[nt]);
            }

            // ---- apply R, mask, rowsum, stage P ----
            bool diag = (jt == qt);
            #pragma unroll
            for (int mi = 0; mi < 2; ++mi) {
                int rl = wy * 32 + mi * 16 + g;
                float Rl = sR[rl], Rh = sR[rl + 8];
                int iglo = i0 + rl, ighi = iglo + 8;
                #pragma unroll
                for (int nt = 0; nt < 4; ++nt) {
                    int jc = wx * 32 + nt * 8 + 2 * tig;
                    int jg = j0 + jc;
                    float p0 = acc[mi][nt][0] * Rl;
                    float p1 = acc[mi][nt][1] * Rl;
                    float p2 = acc[mi][nt][2] * Rh;
                    float p3 = acc[mi][nt][3] * Rh;
                    if (diag) {
                        if (jg     > iglo) p0 = 0.f;
                        if (jg + 1 > iglo) p1 = 0.f;
                        if (jg     > ighi) p2 = 0.f;
                        if (jg + 1 > ighi) p3 = 0.f;
                    }
                    rs[mi][0] += p0 + p1;
                    rs[mi][1] += p2 + p3;
                    *(__half2*)&Ps[rl * STH + jc]       = __floats2half2_rn(p0, p1);
                    *(__half2*)&Ps[(rl + 8) * STH + jc] = __floats2half2_rn(p2, p3);
                }
            }
            __syncthreads();

            // ---- P @ V ----
            unsigned vbase = vb_u32 + cur * TILE_BYTES + vsm_lane;
            #pragma unroll
            for (int ks8 = 0; ks8 < 8; ++ks8) {
                int j8 = ks8 * 16;
                unsigned a[2][4], b[4][2];
                #pragma unroll
                for (int mi = 0; mi < 2; ++mi) {
                    int r0 = wy * 32 + mi * 16 + g;
                    a[mi][0] = *(const unsigned*)&Ps[r0 * STH + j8 + 2 * tig];
                    a[mi][1] = *(const unsigned*)&Ps[(r0 + 8) * STH + j8 + 2 * tig];
                    a[mi][2] = *(const unsigned*)&Ps[r0 * STH + j8 + 8 + 2 * tig];
                    a[mi][3] = *(const unsigned*)&Ps[(r0 + 8) * STH + j8 + 8 + 2 * tig];
                }
                #pragma unroll
                for (int p = 0; p < 2; ++p) {
                    unsigned r4[4];
                    ldsm4t(r4, vbase + (unsigned)((j8 * STH + p * 16) * 2));
                    b[2 * p][0]     = r4[0];
                    b[2 * p][1]     = r4[1];
                    b[2 * p + 1][0] = r4[2];
                    b[2 * p + 1][1] = r4[3];
                }
                #pragma unroll
                for (int mi = 0; mi < 2; ++mi)
                    #pragma unroll
                    for (int nt = 0; nt < 4; ++nt)
                        mma16(Oa[mi][nt], a[mi], b[nt]);
            }
            __syncthreads();   // cur-buffer reads done before reuse
            cur ^= 1;
        }

        // ---- epilogue: partial rowsums + partial O to global ----
        #pragma unroll
        for (int mi = 0; mi < 2; ++mi)
            #pragma unroll
            for (int c = 0; c < 2; ++c) {
                rs[mi][c] += __shfl_xor_sync(0xffffffffu, rs[mi][c], 1);
                rs[mi][c] += __shfl_xor_sync(0xffffffffu, rs[mi][c], 2);
            }
        if (tig == 0) {
            #pragma unroll
            for (int mi = 0; mi < 2; ++mi)
                #pragma unroll
                for (int c = 0; c < 2; ++c) {
                    int row = wy * 32 + mi * 16 + g + 8 * c;
                    rrs[wx * 128 + row] = rs[mi][c];
                }
        }
        __syncthreads();
        if (tid < 128) {
            float tot = rrs[tid] + rrs[128 + tid] + rrs[256 + tid] + rrs[384 + tid];
            g_rsp[half][h][i0 + tid] = tot;
        }
        float* Op = g_Op[half];
        #pragma unroll
        for (int mi = 0; mi < 2; ++mi)
            #pragma unroll
            for (int c = 0; c < 2; ++c) {
                int row = wy * 32 + mi * 16 + g + 8 * c;
                int grow = i0 + row;
                #pragma unroll
                for (int nt = 0; nt < 4; ++nt) {
                    *(float2*)&Op[grow * E_DIM + h * DH + wx * 32 + nt * 8 + 2 * tig]
                        = make_float2(Oa[mi][nt][2 * c], Oa[mi][nt][2 * c + 1]);
                }
            }
    }
}

// =================================================================
// Kernel 4: fixup — 4 rows per block (best measured). grid 512.
// =================================================================
__global__ void fixup_kernel(const float* __restrict__ lnsc,
                             float* __restrict__ out) {
    int ib = blockIdx.x;
    int h = threadIdx.x >> 5, lane = threadIdx.x & 31;
    int c4 = lane * 4;

    float4 p0[4], p1[4];
    float rsum[4], n2v[4];
    #pragma unroll
    for (int rr = 0; rr < 4; ++rr) {
        int i = ib * 4 + rr;
        int base = i * E_DIM + h * DH + c4;
        p0[rr] = *(const float4*)&g_Op[0][base];
        p1[rr] = *(const float4*)&g_Op[1][base];
        rsum[rr] = g_rsp[0][h][i] + g_rsp[1][h][i];
        n2v[rr]  = g_n2[h][i];
    }
    float4 gl = *(const float4*)&lnsc[h * DH + c4];

    float x[4][4], s[4], s2[4];
    #pragma unroll
    for (int rr = 0; rr < 4; ++rr) {
        float denom = fmaxf(fabsf(rsum[rr]), n2v[rr]) + EPS_F;
        float invd = 1.f / denom;
        x[rr][0] = (p0[rr].x + p1[rr].x) * invd;
        x[rr][1] = (p0[rr].y + p1[rr].y) * invd;
        x[rr][2] = (p0[rr].z + p1[rr].z) * invd;
        x[rr][3] = (p0[rr].w + p1[rr].w) * invd;
        s[rr]  = x[rr][0] + x[rr][1] + x[rr][2] + x[rr][3];
        s2[rr] = x[rr][0] * x[rr][0] + x[rr][1] * x[rr][1]
               + x[rr][2] * x[rr][2] + x[rr][3] * x[rr][3];
    }
    #pragma unroll
    for (int o = 16; o > 0; o >>= 1) {
        #pragma unroll
        for (int rr = 0; rr < 4; ++rr) {
            s[rr]  += __shfl_xor_sync(0xffffffffu, s[rr],  o);
            s2[rr] += __shfl_xor_sync(0xffffffffu, s2[rr], o);
        }
    }
    #pragma unroll
    for (int rr = 0; rr < 4; ++rr) {
        float mean = s[rr] * (1.f / 128.f);
        float rstd = rsqrtf(s2[rr] * (1.f / 128.f) - mean * mean + EPS_F);
        int base = (ib * 4 + rr) * E_DIM + h * DH + c4;
        float4 o4;
        o4.x = (x[rr][0] - mean) * rstd * gl.x;
        o4.y = (x[rr][1] - mean) * rstd * gl.y;
        o4.z = (x[rr][2] - mean) * rstd * gl.z;
        o4.w = (x[rr][3] - mean) * rstd * gl.w;
        *(float4*)&out[base] = o4;
    }
}

// =================================================================
extern "C" void kernel_launch(void* const* d_in, const int* in_sizes, int n_in,
                              void* d_out, int out_size) {
    const float* q    = (const float*)d_in[0];
    const float* k    = (const float*)d_in[1];
    const float* v    = (const float*)d_in[2];
    const float* Wi   = (const float*)d_in[3];
    const float* bi   = (const float*)d_in[4];
    const float* Wf   = (const float*)d_in[5];
    const float* bf   = (const float*)d_in[6];
    const float* lnsc = (const float*)d_in[7];
    float* out = (float*)d_out;

    const int gate_smem = (1024 * 16 + 8 * 16 * 33 + 8 * 32 * 20) * 4;  // 102912 B
    const int attn_smem = 6 * TILE_BYTES + 768 * 4;                     // 211968 B

    cudaFuncSetAttribute(gate_kernel, cudaFuncAttributeMaxDynamicSharedMemorySize, gate_smem);
    cudaFuncSetAttribute(attn_kernel, cudaFuncAttributeMaxDynamicSharedMemorySize, attn_smem);

    gate_kernel<<<dim3(128, 3), 256, gate_smem>>>(q, k, v, Wi, Wf);
    scan_kernel<<<8, 1024>>>(bi, bf);
    prep_kernel<<<256, 256>>>(k, v);
    attn_kernel<<<dim3(16, NH), 512, attn_smem>>>(q);
    fixup_kernel<<<S_LEN / 4, 256>>>(lnsc, out);
}